// round 1
// baseline (speedup 1.0000x reference)
#include <cuda_runtime.h>
#include <cuda_bf16.h>
#include <math.h>

// ---------------- problem constants ----------------
#define D 256        // D_IN = D_HID
#define O 10         // D_OUT
#define NS 64        // samples per batch
#define NT 128       // total samples (batch1 then batch2)
#define R 640        // NS * O  (flattened pair-GEMM dim)

// ---------------- scratch (device globals; no allocation allowed) ----------------
__device__ float d_W2T[D * D];            // W2 transposed
__device__ float d_H1[NT * D];            // tanh layer-1 activations
__device__ float d_H2[NT * D];            // tanh layer-2 activations
__device__ float d_G1[NT * O * D];        // dy_a/dz1, per sample
__device__ float d_G2[NT * O * D];        // dy_a/dz2, per sample
__device__ float d_P[2][R * R];           // pair GEMM results per layer
__device__ float d_C[3][NS * NS];         // input dots + 1 per layer

// ---------------- kernel 0: transpose W2 ----------------
__global__ void transpose_kernel(const float* __restrict__ W2) {
    __shared__ float tile[32][33];
    int bx = blockIdx.x * 32, by = blockIdx.y * 32;
    int tx = threadIdx.x, ty = threadIdx.y;  // 32 x 8
#pragma unroll
    for (int i = 0; i < 32; i += 8)
        tile[ty + i][tx] = W2[(by + ty + i) * D + bx + tx];
    __syncthreads();
#pragma unroll
    for (int i = 0; i < 32; i += 8)
        d_W2T[(bx + ty + i) * D + by + tx] = tile[tx][ty + i];
}

// ---------------- kernel 1: per-sample forward + backward ----------------
// one block per sample (128 blocks, 256 threads)
__global__ __launch_bounds__(256) void sample_kernel(
    const float* __restrict__ x1, const float* __restrict__ x2,
    const float* __restrict__ W1, const float* __restrict__ b1,
    const float* __restrict__ W2, const float* __restrict__ b2,
    const float* __restrict__ W3)
{
    __shared__ float xs[D];
    __shared__ float h1s[D];
    __shared__ float g2s[O][D];

    const int s = blockIdx.x;
    const int t = threadIdx.x;
    const float* x = (s < NS) ? (x1 + s * D) : (x2 + (s - NS) * D);

    xs[t] = x[t];
    __syncthreads();

    // h1[t] = tanh(b1[t] + sum_i x[i] * W1[i, t])   (coalesced over t)
    float acc = b1[t];
#pragma unroll 8
    for (int i = 0; i < D; i++) acc += xs[i] * W1[i * D + t];
    float h1 = tanhf(acc);
    h1s[t] = h1;
    d_H1[s * D + t] = h1;
    __syncthreads();

    // h2[t] = tanh(b2[t] + sum_j h1[j] * W2[j, t])
    acc = b2[t];
#pragma unroll 8
    for (int j = 0; j < D; j++) acc += h1s[j] * W2[j * D + t];
    float h2 = tanhf(acc);
    d_H2[s * D + t] = h2;
    float t2 = 1.0f - h2 * h2;

    // G2[a, t] = W3[t, a] * (1 - h2[t]^2)
#pragma unroll
    for (int a = 0; a < O; a++) {
        float g = W3[t * O + a] * t2;
        g2s[a][t] = g;
        d_G2[(s * O + a) * D + t] = g;
    }
    __syncthreads();

    // G1[a, t] = (1 - h1[t]^2) * sum_k W2[t, k] * G2[a, k]
    //          = t1 * sum_k W2T[k, t] * g2s[a][k]   (coalesced W2T reads)
    float t1 = 1.0f - h1 * h1;
    float a10[O];
#pragma unroll
    for (int a = 0; a < O; a++) a10[a] = 0.0f;
#pragma unroll 4
    for (int k = 0; k < D; k++) {
        float w = d_W2T[k * D + t];
#pragma unroll
        for (int a = 0; a < O; a++) a10[a] += w * g2s[a][k];
    }
#pragma unroll
    for (int a = 0; a < O; a++) d_G1[(s * O + a) * D + t] = t1 * a10[a];
}

// ---------------- kernel 2: pairwise input dots (+1 bias term) ----------------
// one block per n (64 blocks, 256 threads = 8 warps; each warp does 8 m's)
__global__ __launch_bounds__(256) void dots_kernel(
    const float* __restrict__ x1, const float* __restrict__ x2)
{
    __shared__ float xa[D], h1a[D], h2a[D];
    const int n = blockIdx.x;
    const int t = threadIdx.x;
    xa[t]  = x1[n * D + t];
    h1a[t] = d_H1[n * D + t];
    h2a[t] = d_H2[n * D + t];
    __syncthreads();

    const int warp = t >> 5, lane = t & 31;
#pragma unroll
    for (int mi = 0; mi < 8; mi++) {
        int m = warp * 8 + mi;
        const float* x2r = x2 + m * D;
        const float* h1r = d_H1 + (NS + m) * D;
        const float* h2r = d_H2 + (NS + m) * D;
        float s0 = 0.f, s1 = 0.f, s2 = 0.f;
#pragma unroll
        for (int k = lane; k < D; k += 32) {
            s0 += xa[k]  * x2r[k];
            s1 += h1a[k] * h1r[k];
            s2 += h2a[k] * h2r[k];
        }
#pragma unroll
        for (int off = 16; off > 0; off >>= 1) {
            s0 += __shfl_down_sync(0xffffffffu, s0, off);
            s1 += __shfl_down_sync(0xffffffffu, s1, off);
            s2 += __shfl_down_sync(0xffffffffu, s2, off);
        }
        if (lane == 0) {
            d_C[0][n * NS + m] = s0 + 1.0f;
            d_C[1][n * NS + m] = s1 + 1.0f;
            d_C[2][n * NS + m] = s2 + 1.0f;
        }
    }
}

// ---------------- kernel 3: P_l = G_l(batch1)[640,256] @ G_l(batch2)[640,256]^T ----
// 64x64 block tile, 16-deep K chunks, 4x4 per thread, grid (10,10,2)
__global__ __launch_bounds__(256) void gemm_kernel() {
    const int layer = blockIdx.z;
    const float* G = (layer == 0) ? d_G1 : d_G2;
    const float* A = G;                 // batch-1 rows (0..639)
    const float* B = G + R * D;         // batch-2 rows
    float* P = d_P[layer];

    __shared__ __align__(16) float As[16][68];
    __shared__ __align__(16) float Bs[16][68];

    const int tid = threadIdx.x;
    const int tx = tid & 15, ty = tid >> 4;
    const int r0 = blockIdx.y * 64, c0 = blockIdx.x * 64;
    const int lrow = tid >> 2;          // 0..63
    const int lk   = (tid & 3) * 4;     // 0,4,8,12

    float acc[4][4] = {};

    for (int kc = 0; kc < D; kc += 16) {
        float4 a4 = *(const float4*)&A[(r0 + lrow) * D + kc + lk];
        float4 b4 = *(const float4*)&B[(c0 + lrow) * D + kc + lk];
        As[lk + 0][lrow] = a4.x; As[lk + 1][lrow] = a4.y;
        As[lk + 2][lrow] = a4.z; As[lk + 3][lrow] = a4.w;
        Bs[lk + 0][lrow] = b4.x; Bs[lk + 1][lrow] = b4.y;
        Bs[lk + 2][lrow] = b4.z; Bs[lk + 3][lrow] = b4.w;
        __syncthreads();
#pragma unroll
        for (int k = 0; k < 16; k++) {
            float4 av = *(const float4*)&As[k][ty * 4];
            float4 bv = *(const float4*)&Bs[k][tx * 4];
            float a[4] = {av.x, av.y, av.z, av.w};
            float b[4] = {bv.x, bv.y, bv.z, bv.w};
#pragma unroll
            for (int i = 0; i < 4; i++)
#pragma unroll
                for (int j = 0; j < 4; j++)
                    acc[i][j] += a[i] * b[j];
        }
        __syncthreads();
    }

#pragma unroll
    for (int i = 0; i < 4; i++) {
        float4 v = make_float4(acc[i][0], acc[i][1], acc[i][2], acc[i][3]);
        *(float4*)&P[(r0 + ty * 4 + i) * R + c0 + tx * 4] = v;
    }
}

// ---------------- kernel 4: combine ----------------
// out[n,m,a,b] = C0*P0[(n*10+a),(m*10+b)] + C1*P1[...] + (a==b)*C2
__global__ __launch_bounds__(256) void combine_kernel(float* __restrict__ out) {
    int idx = blockIdx.x * 256 + threadIdx.x;
    if (idx >= NS * NS * O * O) return;
    int n  = idx / (NS * O * O);
    int r  = idx % (NS * O * O);
    int m  = r / (O * O);
    int ab = r % (O * O);
    int a = ab / O, b = ab % O;
    int pidx = (n * O + a) * R + (m * O + b);
    int cidx = n * NS + m;
    float v = d_C[0][cidx] * d_P[0][pidx]
            + d_C[1][cidx] * d_P[1][pidx];
    if (a == b) v += d_C[2][cidx];
    out[idx] = v;
}

// ---------------- launcher ----------------
extern "C" void kernel_launch(void* const* d_in, const int* in_sizes, int n_in,
                              void* d_out, int out_size) {
    const float* x1 = (const float*)d_in[0];
    const float* x2 = (const float*)d_in[1];
    const float* W1 = (const float*)d_in[2];
    const float* b1 = (const float*)d_in[3];
    const float* W2 = (const float*)d_in[4];
    const float* b2 = (const float*)d_in[5];
    const float* W3 = (const float*)d_in[6];
    // d_in[7] = b3: Jacobian w.r.t. b3 is constant -> value unused
    float* out = (float*)d_out;

    transpose_kernel<<<dim3(8, 8), dim3(32, 8)>>>(W2);
    sample_kernel<<<NT, 256>>>(x1, x2, W1, b1, W2, b2, W3);
    dots_kernel<<<NS, 256>>>(x1, x2);
    gemm_kernel<<<dim3(10, 10, 2), 256>>>();
    combine_kernel<<<(NS * NS * O * O + 255) / 256, 256>>>(out);
}

// round 2
// speedup vs baseline: 1.3021x; 1.3021x over previous
#include <cuda_runtime.h>
#include <math.h>

#define D 256
#define O 10
#define NS 64
#define R 640   // NS*O

// ---------------- scratch ----------------
__device__ float d_W2P[D * D];     // float4 at (k4*D + t) holds W2[t][4k4..4k4+3]
__device__ float d_H1[2 * NS * D];
__device__ float d_H2[2 * NS * D];
__device__ float d_G1[2 * R * D];  // batch1 rows then batch2 rows
__device__ float d_G2[2 * R * D];
__device__ float d_C[3][NS * NS];

// ================= K1: W2 repack (blocks 0..63) + forward (blocks 64..191) ========
__global__ __launch_bounds__(256) void k1_fwd(
    const float* __restrict__ x1, const float* __restrict__ x2,
    const float* __restrict__ W1, const float* __restrict__ b1,
    const float* __restrict__ W2, const float* __restrict__ b2,
    const float* __restrict__ W3)
{
    __shared__ float sm[2 * D];
    const int b = blockIdx.x, t = threadIdx.x;

    if (b < 64) {
        // pack W2 rows into k-major float4s: coalesced reads, strided 16B writes
        int gid = b * 256 + t;
        int k4 = gid & 63, tw = gid >> 6;
        float4 v = *(const float4*)&W2[tw * D + k4 * 4];
        *(float4*)&d_W2P[(k4 * D + tw) * 4] = v;
        return;
    }

    const int s = b - 64;
    const float* x = (s < NS) ? (x1 + s * D) : (x2 + (s - NS) * D);
    sm[t] = x[t];
    __syncthreads();

    float acc = b1[t];
#pragma unroll 8
    for (int i = 0; i < D; i++) acc += sm[i] * W1[i * D + t];
    float h1 = tanhf(acc);
    sm[D + t] = h1;
    d_H1[s * D + t] = h1;
    __syncthreads();

    acc = b2[t];
#pragma unroll 8
    for (int j = 0; j < D; j++) acc += sm[D + j] * W2[j * D + t];
    float h2 = tanhf(acc);
    d_H2[s * D + t] = h2;
    float t2 = 1.0f - h2 * h2;

#pragma unroll
    for (int a = 0; a < O; a++)
        d_G2[(s * O + a) * D + t] = W3[t * O + a] * t2;
}

// ================= K2: G1 backward (blocks 0..255) + pairwise dots (256..319) =====
__global__ __launch_bounds__(256) void k2_bwd_dots(
    const float* __restrict__ x1, const float* __restrict__ x2)
{
    __shared__ float sm[5 * D];
    const int b = blockIdx.x, t = threadIdx.x;

    if (b < 256) {
        // G1[s, a, t] = (1 - h1^2) * sum_k W2[t,k] * G2[s,a,k];  5 a's per CTA
        const int s = b >> 1, half = b & 1;
#pragma unroll
        for (int j = 0; j < 5; j++)
            sm[j * D + t] = d_G2[(s * O + half * 5 + j) * D + t];
        float h1 = d_H1[s * D + t];
        float t1 = 1.0f - h1 * h1;
        __syncthreads();

        float a0 = 0.f, a1 = 0.f, a2 = 0.f, a3 = 0.f, a4 = 0.f;
#pragma unroll 4
        for (int k4 = 0; k4 < 64; k4++) {
            float4 w  = *(const float4*)&d_W2P[(k4 * D + t) * 4];
            float4 g0 = *(const float4*)&sm[0 * D + k4 * 4];
            float4 g1 = *(const float4*)&sm[1 * D + k4 * 4];
            float4 g2 = *(const float4*)&sm[2 * D + k4 * 4];
            float4 g3 = *(const float4*)&sm[3 * D + k4 * 4];
            float4 g4 = *(const float4*)&sm[4 * D + k4 * 4];
            a0 += w.x * g0.x + w.y * g0.y + w.z * g0.z + w.w * g0.w;
            a1 += w.x * g1.x + w.y * g1.y + w.z * g1.z + w.w * g1.w;
            a2 += w.x * g2.x + w.y * g2.y + w.z * g2.z + w.w * g2.w;
            a3 += w.x * g3.x + w.y * g3.y + w.z * g3.z + w.w * g3.w;
            a4 += w.x * g4.x + w.y * g4.y + w.z * g4.z + w.w * g4.w;
        }
        const int base = (s * O + half * 5) * D + t;
        d_G1[base + 0 * D] = t1 * a0;
        d_G1[base + 1 * D] = t1 * a1;
        d_G1[base + 2 * D] = t1 * a2;
        d_G1[base + 3 * D] = t1 * a3;
        d_G1[base + 4 * D] = t1 * a4;
        return;
    }

    // ---- dots: C_l[n,m] = <feat_l(n), feat_l(m)> + 1 ----
    const int n = b - 256;
    float* xa  = sm;
    float* h1a = sm + D;
    float* h2a = sm + 2 * D;
    xa[t]  = x1[n * D + t];
    h1a[t] = d_H1[n * D + t];
    h2a[t] = d_H2[n * D + t];
    __syncthreads();

    const int warp = t >> 5, lane = t & 31;
#pragma unroll
    for (int mi = 0; mi < 8; mi++) {
        int m = warp * 8 + mi;
        const float* x2r = x2 + m * D;
        const float* h1r = d_H1 + (NS + m) * D;
        const float* h2r = d_H2 + (NS + m) * D;
        float s0 = 0.f, s1 = 0.f, s2 = 0.f;
#pragma unroll
        for (int k = lane; k < D; k += 32) {
            s0 += xa[k]  * x2r[k];
            s1 += h1a[k] * h1r[k];
            s2 += h2a[k] * h2r[k];
        }
#pragma unroll
        for (int off = 16; off > 0; off >>= 1) {
            s0 += __shfl_down_sync(0xffffffffu, s0, off);
            s1 += __shfl_down_sync(0xffffffffu, s1, off);
            s2 += __shfl_down_sync(0xffffffffu, s2, off);
        }
        if (lane == 0) {
            d_C[0][n * NS + m] = s0 + 1.0f;
            d_C[1][n * NS + m] = s1 + 1.0f;
            d_C[2][n * NS + m] = s2 + 1.0f;
        }
    }
}

// ================= K3: fused pair-GEMMs (both layers) + NTK combine ===============
// 32x32 output tile, 64 threads, 4x4 micro, 512-deep fused K (layer0 then layer1),
// register-prefetch pipeline over 16 stages of KD=32.
__global__ __launch_bounds__(64) void k3_pair(float* __restrict__ out)
{
    __shared__ float As[32][36];   // k-major, pad 36 (144B rows: 16B aligned, conflict-free reads)
    __shared__ float Bs[32][36];

    const int tid = threadIdx.x;
    const int tx = tid & 7, ty = tid >> 3;
    const int r0 = blockIdx.y * 32, c0 = blockIdx.x * 32;

    float4 ra[4], rb[4];
    float acc0[4][4] = {};
    float acc1[4][4] = {};

#define LDG_STAGE(st) {                                                        \
    const float* G = ((st) < 8) ? d_G1 : d_G2;                                 \
    const int kc = ((st) & 7) * 32;                                            \
    const float* Ag = G + r0 * D + kc;                                         \
    const float* Bg = G + R * D + c0 * D + kc;                                 \
    _Pragma("unroll")                                                          \
    for (int p = 0; p < 4; p++) {                                              \
        int slot = p * 64 + tid; int row = slot >> 3; int kq = slot & 7;       \
        ra[p] = *(const float4*)&Ag[row * D + kq * 4];                         \
        rb[p] = *(const float4*)&Bg[row * D + kq * 4];                         \
    } }

#define STS_STAGE() {                                                          \
    _Pragma("unroll")                                                          \
    for (int p = 0; p < 4; p++) {                                              \
        int slot = p * 64 + tid; int row = slot >> 3; int k0 = (slot & 7) * 4; \
        As[k0 + 0][row] = ra[p].x; As[k0 + 1][row] = ra[p].y;                  \
        As[k0 + 2][row] = ra[p].z; As[k0 + 3][row] = ra[p].w;                  \
        Bs[k0 + 0][row] = rb[p].x; Bs[k0 + 1][row] = rb[p].y;                  \
        Bs[k0 + 2][row] = rb[p].z; Bs[k0 + 3][row] = rb[p].w;                  \
    } }

#define COMPUTE(ACC) {                                                         \
    _Pragma("unroll")                                                          \
    for (int k = 0; k < 32; k++) {                                             \
        float4 a4 = *(const float4*)&As[k][ty * 4];                            \
        float4 b4 = *(const float4*)&Bs[k][tx * 4];                            \
        float av[4] = {a4.x, a4.y, a4.z, a4.w};                                \
        float bv[4] = {b4.x, b4.y, b4.z, b4.w};                                \
        _Pragma("unroll")                                                      \
        for (int i = 0; i < 4; i++)                                            \
            _Pragma("unroll")                                                  \
            for (int j = 0; j < 4; j++)                                        \
                ACC[i][j] += av[i] * bv[j];                                    \
    } }

    LDG_STAGE(0); STS_STAGE(); __syncthreads();

    for (int st = 0; st < 8; st++) {              // layer 0 (G1)
        LDG_STAGE(st + 1);
        COMPUTE(acc0);
        __syncthreads(); STS_STAGE(); __syncthreads();
    }
    for (int st = 8; st < 16; st++) {             // layer 1 (G2)
        if (st < 15) LDG_STAGE(st + 1);
        COMPUTE(acc1);
        if (st < 15) { __syncthreads(); STS_STAGE(); __syncthreads(); }
    }

    // ---- epilogue: out[n,m,a,b] = C0*P0 + C1*P1 + (a==b)*C2 ----
#pragma unroll
    for (int i = 0; i < 4; i++) {
        int row = r0 + ty * 4 + i;               // = n*10 + a
        int n = row / 10, a = row - n * 10;
#pragma unroll
        for (int j = 0; j < 4; j++) {
            int col = c0 + tx * 4 + j;           // = m*10 + b
            int m = col / 10, bb = col - m * 10;
            int ci = n * NS + m;
            float v = d_C[0][ci] * acc0[i][j] + d_C[1][ci] * acc1[i][j];
            if (a == bb) v += d_C[2][ci];
            out[(n * NS + m) * 100 + a * 10 + bb] = v;
        }
    }
#undef LDG_STAGE
#undef STS_STAGE
#undef COMPUTE
}

// ---------------- launcher ----------------
extern "C" void kernel_launch(void* const* d_in, const int* in_sizes, int n_in,
                              void* d_out, int out_size) {
    const float* x1 = (const float*)d_in[0];
    const float* x2 = (const float*)d_in[1];
    const float* W1 = (const float*)d_in[2];
    const float* b1 = (const float*)d_in[3];
    const float* W2 = (const float*)d_in[4];
    const float* b2 = (const float*)d_in[5];
    const float* W3 = (const float*)d_in[6];
    float* out = (float*)d_out;

    k1_fwd<<<192, 256>>>(x1, x2, W1, b1, W2, b2, W3);
    k2_bwd_dots<<<320, 256>>>(x1, x2);
    k3_pair<<<dim3(20, 20), 64>>>(out);
}